// round 15
// baseline (speedup 1.0000x reference)
#include <cuda_runtime.h>
#include <cuda_fp16.h>
#include <cstdint>

#define VOCAB   100000
#define NCODES  100000
#define NANC    8
#define EMB     128

// fp16 projected leaf table + interleaved {P2,E} ancestor table.
// g_PE row (512B): chunk c = halves [8c,8c+8) = { p2[4c..4c+4), e[4c..4c+4) }
// -> lane l's uint4 at byte 16l yields p2 and e for its 4 columns in ONE load.
// Footprint: 26 + 51 = 77MB -> L2-resident.
__device__ __align__(16) __half g_P1[(size_t)VOCAB * EMB];
__device__ __align__(16) __half g_PE[(size_t)VOCAB * 2 * EMB];

__device__ __forceinline__ float tanh_fast(float x) {
    float y;
    asm("tanh.approx.f32 %0, %1;" : "=f"(y) : "f"(x));
    return y;
}
__device__ __forceinline__ __half2 h2tanh_fast(__half2 x) {
    unsigned r;
    asm("tanh.approx.f16x2 %0, %1;" : "=r"(r) : "r"(*(unsigned*)&x));
    return *(__half2*)&r;
}

// ---------------------------------------------------------------------------
// Fused projection (mma.sync HMMA; tcgen05 ISA unavailable under .target sm_103):
//   P1 = W_emb @ W1 -> g_P1;  P2 = W_emb @ W2 -> g_PE (interleaved);
//   E  = fp16(W_emb)          -> g_PE (interleaved, written in stage A).
// One block per 64 rows; warps 0-3 half 0, warps 4-7 half 1.
// ---------------------------------------------------------------------------
#define AS_STRIDE 132
#define BP_STRIDE 132
#define SM_AS_BYTES (64 * AS_STRIDE * 2)
#define SM_TOT      (SM_AS_BYTES + 2 * 32 * BP_STRIDE * 8)

__global__ __launch_bounds__(256) void proj_kernel(const float* __restrict__ A,
                                                   const float* __restrict__ Watt) {
    extern __shared__ char smraw[];
    __half* As = (__half*)smraw;
    uint2*  Bp = (uint2*)(smraw + SM_AS_BYTES);

    const int m0 = blockIdx.x * 64;
    const int tid = threadIdx.x;
    const int wid = tid >> 5;
    const int lane = tid & 31;

    // ---- stage A (64 rows) as fp16 + emit E into g_PE (interleaved) ----
#pragma unroll
    for (int i = 0; i < 8; i++) {
        int e = tid + i * 256;          // [0, 2048)
        int m = e >> 5;
        int kc = (e & 31) * 4;          // multiple of 4
        int gm = m0 + m; if (gm >= VOCAB) gm = VOCAB - 1;
        float4 v = __ldg((const float4*)(A + (size_t)gm * EMB + kc));
        __half2 h0 = __floats2half2_rn(v.x, v.y);
        __half2 h1 = __floats2half2_rn(v.z, v.w);
        uint2 pk; pk.x = *(unsigned*)&h0; pk.y = *(unsigned*)&h1;
        *(uint2*)&As[m * AS_STRIDE + kc] = pk;
        if (m0 + m < VOCAB) {
            // e[kc..kc+4) -> row byte offset 16*(kc/4) + 8
            char* row = (char*)&g_PE[(size_t)(m0 + m) * 2 * EMB];
            *(uint2*)(row + 4 * kc + 8) = pk;
        }
    }

    // ---- stage B fragment pairs for both halves ----
#pragma unroll
    for (int i = 0; i < 32; i++) {
        int e = tid + i * 256;          // [0, 8192)
        int h   = e >> 12;
        int rem = e & 4095;
        int j   = rem >> 7;             // 0..31
        int n   = rem & 127;
        int kpa = (j >> 2) * 8 + (j & 3);
        const float* Wh = Watt + (size_t)h * 128 * 128;
        float w0 = __ldg(Wh + (size_t)(2 * kpa)     * 128 + n);
        float w1 = __ldg(Wh + (size_t)(2 * kpa + 1) * 128 + n);
        float w2 = __ldg(Wh + (size_t)(2 * kpa + 8) * 128 + n);
        float w3 = __ldg(Wh + (size_t)(2 * kpa + 9) * 128 + n);
        __half2 ha = __floats2half2_rn(w0, w1);
        __half2 hb = __floats2half2_rn(w2, w3);
        uint2 pr; pr.x = *(unsigned*)&ha; pr.y = *(unsigned*)&hb;
        Bp[(h * 32 + j) * BP_STRIDE + n] = pr;
    }
    __syncthreads();

    // ---- mma mainloop ----
    const int g = lane >> 2;
    const int q = lane & 3;
    const int t2 = q * 2;
    const int half = wid >> 2;
    const int w16 = (wid & 3) * 16;
    const uint2* BpH = Bp + half * 32 * BP_STRIDE;

    float c[16][4];
#pragma unroll
    for (int nt = 0; nt < 16; nt++)
#pragma unroll
        for (int j = 0; j < 4; j++) c[nt][j] = 0.0f;

#pragma unroll
    for (int ks = 0; ks < 8; ks++) {
        const int k0 = ks * 16;
        const unsigned a0 = *(const unsigned*)&As[(w16 + g)     * AS_STRIDE + k0 + t2];
        const unsigned a1 = *(const unsigned*)&As[(w16 + g + 8) * AS_STRIDE + k0 + t2];
        const unsigned a2 = *(const unsigned*)&As[(w16 + g)     * AS_STRIDE + k0 + t2 + 8];
        const unsigned a3 = *(const unsigned*)&As[(w16 + g + 8) * AS_STRIDE + k0 + t2 + 8];
        const uint2* brow = BpH + (ks * 4 + q) * BP_STRIDE;
#pragma unroll
        for (int nt = 0; nt < 16; nt++) {
            const uint2 b = brow[nt * 8 + g];
            asm volatile(
                "mma.sync.aligned.m16n8k16.row.col.f32.f16.f16.f32 "
                "{%0,%1,%2,%3}, {%4,%5,%6,%7}, {%8,%9}, {%0,%1,%2,%3};"
                : "+f"(c[nt][0]), "+f"(c[nt][1]), "+f"(c[nt][2]), "+f"(c[nt][3])
                : "r"(a0), "r"(a1), "r"(a2), "r"(a3), "r"(b.x), "r"(b.y));
        }
    }

    // ---- epilogue ----
    const int row0 = m0 + w16 + g;
    const int row1 = row0 + 8;
    if (half == 0) {
        // P1: plain layout
#pragma unroll
        for (int nt = 0; nt < 16; nt++) {
            const int col = nt * 8 + t2;
            if (row0 < VOCAB) {
                __half2 h = __floats2half2_rn(c[nt][0], c[nt][1]);
                *(unsigned*)&g_P1[(size_t)row0 * EMB + col] = *(unsigned*)&h;
            }
            if (row1 < VOCAB) {
                __half2 h = __floats2half2_rn(c[nt][2], c[nt][3]);
                *(unsigned*)&g_P1[(size_t)row1 * EMB + col] = *(unsigned*)&h;
            }
        }
    } else {
        // P2 -> g_PE interleaved: p2[col] at row byte 16*(col/4) + (col&3)*2
#pragma unroll
        for (int nt = 0; nt < 16; nt++) {
            const int col = nt * 8 + t2;                 // even; (col,col+1) same chunk
            const int boff = 16 * (col >> 2) + (col & 3) * 2;
            if (row0 < VOCAB) {
                __half2 h = __floats2half2_rn(c[nt][0], c[nt][1]);
                *(unsigned*)((char*)&g_PE[(size_t)row0 * 2 * EMB] + boff) = *(unsigned*)&h;
            }
            if (row1 < VOCAB) {
                __half2 h = __floats2half2_rn(c[nt][2], c[nt][3]);
                *(unsigned*)((char*)&g_PE[(size_t)row1 * 2 * EMB] + boff) = *(unsigned*)&h;
            }
        }
    }
}

// ---------------------------------------------------------------------------
// Attention pass: one warp per code; lane l owns columns [4l, 4l+4).
// Gathers: leaf -> uint2 from g_P1; ancestor -> ONE uint4 from g_PE ({p2,e}).
// MLP math in packed fp16 (HADD2 / tanh.approx.f16x2 / HFMA2); butterfly,
// softmax and output accumulation stay f32.
// ---------------------------------------------------------------------------
__global__ __launch_bounds__(128, 5) void attn_kernel(const float* __restrict__ b_att,
                                                      const float* __restrict__ v_att,
                                                      const void* __restrict__ leaves,
                                                      const void* __restrict__ ancestors,
                                                      float* __restrict__ out) {
    const int warp = (blockIdx.x * blockDim.x + threadIdx.x) >> 5;
    const int lane = threadIdx.x & 31;
    if (warp >= NCODES) return;
    const int c = lane * 4;

    const float4 bv = __ldg((const float4*)(b_att + c));
    const float4 vv = __ldg((const float4*)(v_att + c));
    const __half2 bv01 = __floats2half2_rn(bv.x, bv.y);
    const __half2 bv23 = __floats2half2_rn(bv.z, bv.w);
    const __half2 vv01 = __floats2half2_rn(vv.x, vv.y);
    const __half2 vv23 = __floats2half2_rn(vv.z, vv.w);

    // ---- dtype probe + ballot ----
    int pl = 0, pa = 0;
    if (lane < 8) {
        const size_t dw = (size_t)warp * 8 + lane;
        pl = __ldg((const int*)leaves + dw);
        pa = __ldg((const int*)ancestors + dw);
    }
    const unsigned bl = __ballot_sync(0xffffffffu, pl != 0);
    const unsigned ba = __ballot_sync(0xffffffffu, pa != 0);
    const bool is64 = (((bl | ba) & 0xAAu) == 0u);

    int wl, wa, mul;
    if (is64) {
        wl = 0; wa = 0;
        if (lane < 16) {
            const size_t dw = (size_t)warp * 16 + lane;
            wl = __ldg((const int*)leaves + dw);
            wa = __ldg((const int*)ancestors + dw);
        }
        mul = 2;
    } else {
        wl = pl; wa = pa; mul = 1;
    }
    int li[NANC], ai[NANC];
#pragma unroll
    for (int a = 0; a < NANC; a++) {
        li[a] = __shfl_sync(0xffffffffu, wl, a * mul);
        ai[a] = __shfl_sync(0xffffffffu, wa, a * mul);
        li[a] = min(max(li[a], 0), VOCAB - 1);
        ai[a] = min(max(ai[a], 0), VOCAB - 1);
    }

    // ---- batch gathers: 8 uint2 (leaf P1) + 8 uint4 (ancestor {P2,E}) ----
    uint2 p1v[NANC];
    uint4 pe[NANC];
#pragma unroll
    for (int a = 0; a < NANC; a++)
        p1v[a] = __ldg((const uint2*)(g_P1 + (size_t)li[a] * EMB + c));
#pragma unroll
    for (int a = 0; a < NANC; a++)
        pe[a] = __ldg((const uint4*)((const char*)&g_PE[(size_t)ai[a] * 2 * EMB] + lane * 16));

    // ---- fp16 MLP + per-lane partial dots ----
    float d[NANC];
#pragma unroll
    for (int a = 0; a < NANC; a++) {
        const __half2 x01 = __hadd2(__hadd2(*(const __half2*)&p1v[a].x,
                                            *(const __half2*)&pe[a].x), bv01);
        const __half2 x23 = __hadd2(__hadd2(*(const __half2*)&p1v[a].y,
                                            *(const __half2*)&pe[a].y), bv23);
        const __half2 t01 = h2tanh_fast(x01);
        const __half2 t23 = h2tanh_fast(x23);
        const __half2 dh = __hfma2(t01, vv01, __hmul2(t23, vv23));
        d[a] = __half2float(__low2half(dh)) + __half2float(__high2half(dh));
    }

    // ---- parallel f32 butterfly reductions ----
#pragma unroll
    for (int m = 16; m >= 1; m >>= 1) {
#pragma unroll
        for (int a = 0; a < NANC; a++)
            d[a] += __shfl_xor_sync(0xffffffffu, d[a], m);
    }

    // ---- softmax + weighted sum (f32) ----
    float mx = d[0];
#pragma unroll
    for (int a = 1; a < NANC; a++) mx = fmaxf(mx, d[a]);
    float sum = 0.0f;
#pragma unroll
    for (int a = 0; a < NANC; a++) { d[a] = __expf(d[a] - mx); sum += d[a]; }
    const float inv = 1.0f / sum;

    float4 accv = make_float4(0.f, 0.f, 0.f, 0.f);
#pragma unroll
    for (int a = 0; a < NANC; a++) {
        const float w = d[a] * inv;
        const float2 ea = __half22float2(*(const __half2*)&pe[a].z);
        const float2 eb = __half22float2(*(const __half2*)&pe[a].w);
        accv.x += w * ea.x;
        accv.y += w * ea.y;
        accv.z += w * eb.x;
        accv.w += w * eb.y;
    }
    *(float4*)(out + (size_t)warp * EMB + c) = accv;
}

extern "C" void kernel_launch(void* const* d_in, const int* in_sizes, int n_in,
                              void* d_out, int out_size) {
    const float* W_emb = nullptr;
    const float* W_att = nullptr;
    const float* b_att = nullptr;
    const float* v_att = nullptr;
    const void*  leaves = nullptr;
    const void*  ancestors = nullptr;

    for (int i = 0; i < n_in; i++) {
        const int s = in_sizes[i];
        if (s == VOCAB * EMB)            { W_emb = (const float*)d_in[i]; }
        else if (s == 2 * EMB * EMB)     { W_att = (const float*)d_in[i]; }
        else if (s == EMB)               { if (!b_att) b_att = (const float*)d_in[i];
                                           else        v_att = (const float*)d_in[i]; }
        else if (s == NCODES * NANC)     { if (!leaves) leaves = d_in[i];
                                           else         ancestors = d_in[i]; }
    }
    if (!W_emb)     W_emb     = (const float*)d_in[0];
    if (!W_att)     W_att     = (const float*)d_in[1];
    if (!b_att)     b_att     = (const float*)d_in[2];
    if (!v_att)     v_att     = (const float*)d_in[3];
    if (!leaves)    leaves    = d_in[4];
    if (!ancestors) ancestors = d_in[5];

    float* out = (float*)d_out;

    cudaFuncSetAttribute(proj_kernel, cudaFuncAttributeMaxDynamicSharedMemorySize, SM_TOT);
    proj_kernel<<<(VOCAB + 63) / 64, 256, SM_TOT>>>(W_emb, W_att);

    const int total_threads = NCODES * 32;
    attn_kernel<<<(total_threads + 127) / 128, 128>>>(b_att, v_att,
                                                      leaves, ancestors, out);
}

// round 16
// speedup vs baseline: 1.0053x; 1.0053x over previous
#include <cuda_runtime.h>
#include <cuda_fp16.h>
#include <cstdint>

#define VOCAB   100000
#define NCODES  100000
#define NANC    8
#define EMB     128

// fp16 projected embeddings + fp16 W_emb copy. 78MB -> L2-resident.
__device__ __align__(16) __half g_P1[(size_t)VOCAB * EMB];
__device__ __align__(16) __half g_P2[(size_t)VOCAB * EMB];
__device__ __align__(16) __half g_E [(size_t)VOCAB * EMB];

__device__ __forceinline__ __half2 h2tanh_fast(__half2 x) {
    unsigned r;
    asm("tanh.approx.f16x2 %0, %1;" : "=r"(r) : "r"(*(unsigned*)&x));
    return *(__half2*)&r;
}

// ---------------------------------------------------------------------------
// Fused projection (mma.sync HMMA; tcgen05 unavailable under .target sm_103):
//   P1 = W_emb @ W1, P2 = W_emb @ W2, g_E = fp16(W_emb)  [R14 version, frozen]
// One block per 64 rows; warps 0-3 half 0, warps 4-7 half 1.
// ---------------------------------------------------------------------------
#define AS_STRIDE 132
#define BP_STRIDE 132
#define SM_AS_BYTES (64 * AS_STRIDE * 2)
#define SM_TOT      (SM_AS_BYTES + 2 * 32 * BP_STRIDE * 8)

__global__ __launch_bounds__(256) void proj_kernel(const float* __restrict__ A,
                                                   const float* __restrict__ Watt) {
    extern __shared__ char smraw[];
    __half* As = (__half*)smraw;
    uint2*  Bp = (uint2*)(smraw + SM_AS_BYTES);

    const int m0 = blockIdx.x * 64;
    const int tid = threadIdx.x;
    const int wid = tid >> 5;
    const int lane = tid & 31;

    // ---- stage A (64 rows) as fp16 + emit g_E (free) ----
#pragma unroll
    for (int i = 0; i < 8; i++) {
        int e = tid + i * 256;
        int m = e >> 5;
        int kc = (e & 31) * 4;
        int gm = m0 + m; if (gm >= VOCAB) gm = VOCAB - 1;
        float4 v = __ldg((const float4*)(A + (size_t)gm * EMB + kc));
        __half2 h0 = __floats2half2_rn(v.x, v.y);
        __half2 h1 = __floats2half2_rn(v.z, v.w);
        uint2 pk; pk.x = *(unsigned*)&h0; pk.y = *(unsigned*)&h1;
        *(uint2*)&As[m * AS_STRIDE + kc] = pk;
        if (m0 + m < VOCAB)
            *(uint2*)&g_E[(size_t)(m0 + m) * EMB + kc] = pk;
    }

    // ---- stage B fragment pairs for both halves ----
#pragma unroll
    for (int i = 0; i < 32; i++) {
        int e = tid + i * 256;
        int h   = e >> 12;
        int rem = e & 4095;
        int j   = rem >> 7;
        int n   = rem & 127;
        int kpa = (j >> 2) * 8 + (j & 3);
        const float* Wh = Watt + (size_t)h * 128 * 128;
        float w0 = __ldg(Wh + (size_t)(2 * kpa)     * 128 + n);
        float w1 = __ldg(Wh + (size_t)(2 * kpa + 1) * 128 + n);
        float w2 = __ldg(Wh + (size_t)(2 * kpa + 8) * 128 + n);
        float w3 = __ldg(Wh + (size_t)(2 * kpa + 9) * 128 + n);
        __half2 ha = __floats2half2_rn(w0, w1);
        __half2 hb = __floats2half2_rn(w2, w3);
        uint2 pr; pr.x = *(unsigned*)&ha; pr.y = *(unsigned*)&hb;
        Bp[(h * 32 + j) * BP_STRIDE + n] = pr;
    }
    __syncthreads();

    // ---- mma mainloop ----
    const int g = lane >> 2;
    const int q = lane & 3;
    const int t2 = q * 2;
    const int half = wid >> 2;
    const int w16 = (wid & 3) * 16;
    const uint2* BpH = Bp + half * 32 * BP_STRIDE;

    float c[16][4];
#pragma unroll
    for (int nt = 0; nt < 16; nt++)
#pragma unroll
        for (int j = 0; j < 4; j++) c[nt][j] = 0.0f;

#pragma unroll
    for (int ks = 0; ks < 8; ks++) {
        const int k0 = ks * 16;
        const unsigned a0 = *(const unsigned*)&As[(w16 + g)     * AS_STRIDE + k0 + t2];
        const unsigned a1 = *(const unsigned*)&As[(w16 + g + 8) * AS_STRIDE + k0 + t2];
        const unsigned a2 = *(const unsigned*)&As[(w16 + g)     * AS_STRIDE + k0 + t2 + 8];
        const unsigned a3 = *(const unsigned*)&As[(w16 + g + 8) * AS_STRIDE + k0 + t2 + 8];
        const uint2* brow = BpH + (ks * 4 + q) * BP_STRIDE;
#pragma unroll
        for (int nt = 0; nt < 16; nt++) {
            const uint2 b = brow[nt * 8 + g];
            asm volatile(
                "mma.sync.aligned.m16n8k16.row.col.f32.f16.f16.f32 "
                "{%0,%1,%2,%3}, {%4,%5,%6,%7}, {%8,%9}, {%0,%1,%2,%3};"
                : "+f"(c[nt][0]), "+f"(c[nt][1]), "+f"(c[nt][2]), "+f"(c[nt][3])
                : "r"(a0), "r"(a1), "r"(a2), "r"(a3), "r"(b.x), "r"(b.y));
        }
    }

    // ---- epilogue: f32 accum -> fp16 pairs ----
    __half* P = half ? g_P2 : g_P1;
    const int row0 = m0 + w16 + g;
    const int row1 = row0 + 8;
#pragma unroll
    for (int nt = 0; nt < 16; nt++) {
        const int col = nt * 8 + t2;
        if (row0 < VOCAB) {
            __half2 h = __floats2half2_rn(c[nt][0], c[nt][1]);
            *(unsigned*)&P[(size_t)row0 * EMB + col] = *(unsigned*)&h;
        }
        if (row1 < VOCAB) {
            __half2 h = __floats2half2_rn(c[nt][2], c[nt][3]);
            *(unsigned*)&P[(size_t)row1 * EMB + col] = *(unsigned*)&h;
        }
    }
}

// ---------------------------------------------------------------------------
// Attention pass: TWO codes per warp. Half h = lane>>4 owns code 2*warp+h;
// sub-lane s = lane&15 owns columns [8s, 8s+8) (one uint4 = 8 fp16 per row).
// One LDG fetches BOTH halves' rows (2 x 256B) -> per-code LDG/address cost
// halves vs 1-code/warp. Butterfly is 4 stages within 16-lane groups.
// fp16 MLP math; f32 reduction/softmax/output. p1v/p2v die before ev loads.
// ---------------------------------------------------------------------------
__global__ __launch_bounds__(128, 4) void attn_kernel(const float* __restrict__ b_att,
                                                      const float* __restrict__ v_att,
                                                      const void* __restrict__ leaves,
                                                      const void* __restrict__ ancestors,
                                                      float* __restrict__ out) {
    const int warp = (blockIdx.x * blockDim.x + threadIdx.x) >> 5;   // 0..49999
    const int lane = threadIdx.x & 31;
    if (warp >= NCODES / 2) return;
    const int h = lane >> 4;
    const int s = lane & 15;
    const int c = s * 8;

    // ---- per-lane b/v (cols c..c+8) as packed fp16 ----
    const float4 b0 = __ldg((const float4*)(b_att + c));
    const float4 b1 = __ldg((const float4*)(b_att + c + 4));
    const float4 v0 = __ldg((const float4*)(v_att + c));
    const float4 v1 = __ldg((const float4*)(v_att + c + 4));
    const __half2 bh0 = __floats2half2_rn(b0.x, b0.y);
    const __half2 bh1 = __floats2half2_rn(b0.z, b0.w);
    const __half2 bh2 = __floats2half2_rn(b1.x, b1.y);
    const __half2 bh3 = __floats2half2_rn(b1.z, b1.w);
    const __half2 vh0 = __floats2half2_rn(v0.x, v0.y);
    const __half2 vh1 = __floats2half2_rn(v0.z, v0.w);
    const __half2 vh2 = __floats2half2_rn(v1.x, v1.y);
    const __half2 vh3 = __floats2half2_rn(v1.z, v1.w);

    // ---- dtype probe: dwords [warp*16, warp*16+16) -- in-bounds both ways ----
    int pl = 0, pa = 0;
    if (lane < 16) {
        const size_t dw = (size_t)warp * 16 + lane;
        pl = __ldg((const int*)leaves + dw);
        pa = __ldg((const int*)ancestors + dw);
    }
    const unsigned nzb = __ballot_sync(0xffffffffu, (pl | pa) != 0);
    const bool is64 = ((nzb & 0xAAAAu) == 0u);   // odd dwords (int64 high words) all zero

    // ---- index fetch + per-half shuffle broadcast ----
    int wl, wa, hbase, mul;
    if (is64) {
        const size_t dw = (size_t)warp * 32 + lane;   // 2 int64 rows = 32 dwords
        wl = __ldg((const int*)leaves + dw);
        wa = __ldg((const int*)ancestors + dw);
        hbase = h * 16; mul = 2;
    } else {
        wl = pl; wa = pa;                              // probe WAS both int32 rows
        hbase = h * 8; mul = 1;
    }
    int li[NANC], ai[NANC];
#pragma unroll
    for (int a = 0; a < NANC; a++) {
        const int src = hbase + a * mul;
        li[a] = __shfl_sync(0xffffffffu, wl, src);
        ai[a] = __shfl_sync(0xffffffffu, wa, src);
        li[a] = min(max(li[a], 0), VOCAB - 1);
        ai[a] = min(max(ai[a], 0), VOCAB - 1);
    }

    // ---- batch P1/P2 gathers (uint4 = 8 fp16/lane; 2 rows per LDG) ----
    uint4 p1v[NANC], p2v[NANC];
#pragma unroll
    for (int a = 0; a < NANC; a++)
        p1v[a] = __ldg((const uint4*)((const char*)g_P1 + (size_t)li[a] * 256 + s * 16));
#pragma unroll
    for (int a = 0; a < NANC; a++)
        p2v[a] = __ldg((const uint4*)((const char*)g_P2 + (size_t)ai[a] * 256 + s * 16));

    // ---- fp16 MLP + per-lane partial dots (p1v/p2v die here) ----
    float d[NANC];
#pragma unroll
    for (int a = 0; a < NANC; a++) {
        const __half2* p1 = (const __half2*)&p1v[a];
        const __half2* p2 = (const __half2*)&p2v[a];
        const __half2 t0 = h2tanh_fast(__hadd2(__hadd2(p1[0], p2[0]), bh0));
        const __half2 t1 = h2tanh_fast(__hadd2(__hadd2(p1[1], p2[1]), bh1));
        const __half2 t2 = h2tanh_fast(__hadd2(__hadd2(p1[2], p2[2]), bh2));
        const __half2 t3 = h2tanh_fast(__hadd2(__hadd2(p1[3], p2[3]), bh3));
        __half2 dh = __hmul2(t0, vh0);
        dh = __hfma2(t1, vh1, dh);
        dh = __hfma2(t2, vh2, dh);
        dh = __hfma2(t3, vh3, dh);
        const float2 df = __half22float2(dh);
        d[a] = df.x + df.y;
    }

    // ---- batch E gathers (overlap reduction latency) ----
    uint4 ev[NANC];
#pragma unroll
    for (int a = 0; a < NANC; a++)
        ev[a] = __ldg((const uint4*)((const char*)g_E + (size_t)ai[a] * 256 + s * 16));

    // ---- parallel butterfly reductions within 16-lane halves ----
#pragma unroll
    for (int m = 8; m >= 1; m >>= 1) {
#pragma unroll
        for (int a = 0; a < NANC; a++)
            d[a] += __shfl_xor_sync(0xffffffffu, d[a], m);
    }

    // ---- softmax (per half, redundant across its 16 lanes) ----
    float mx = d[0];
#pragma unroll
    for (int a = 1; a < NANC; a++) mx = fmaxf(mx, d[a]);
    float sum = 0.0f;
#pragma unroll
    for (int a = 0; a < NANC; a++) { d[a] = __expf(d[a] - mx); sum += d[a]; }
    const float inv = 1.0f / sum;

    // ---- weighted sum over 8 owned columns ----
    float acc[8];
#pragma unroll
    for (int j = 0; j < 8; j++) acc[j] = 0.0f;
#pragma unroll
    for (int a = 0; a < NANC; a++) {
        const float w = d[a] * inv;
        const __half2* eh = (const __half2*)&ev[a];
#pragma unroll
        for (int j = 0; j < 4; j++) {
            const float2 e2 = __half22float2(eh[j]);
            acc[2 * j]     += w * e2.x;
            acc[2 * j + 1] += w * e2.y;
        }
    }
    float* orow = out + (size_t)(2 * warp + h) * EMB + c;
    *(float4*)orow       = make_float4(acc[0], acc[1], acc[2], acc[3]);
    *(float4*)(orow + 4) = make_float4(acc[4], acc[5], acc[6], acc[7]);
}

extern "C" void kernel_launch(void* const* d_in, const int* in_sizes, int n_in,
                              void* d_out, int out_size) {
    const float* W_emb = nullptr;
    const float* W_att = nullptr;
    const float* b_att = nullptr;
    const float* v_att = nullptr;
    const void*  leaves = nullptr;
    const void*  ancestors = nullptr;

    for (int i = 0; i < n_in; i++) {
        const int s = in_sizes[i];
        if (s == VOCAB * EMB)            { W_emb = (const float*)d_in[i]; }
        else if (s == 2 * EMB * EMB)     { W_att = (const float*)d_in[i]; }
        else if (s == EMB)               { if (!b_att) b_att = (const float*)d_in[i];
                                           else        v_att = (const float*)d_in[i]; }
        else if (s == NCODES * NANC)     { if (!leaves) leaves = d_in[i];
                                           else         ancestors = d_in[i]; }
    }
    if (!W_emb)     W_emb     = (const float*)d_in[0];
    if (!W_att)     W_att     = (const float*)d_in[1];
    if (!b_att)     b_att     = (const float*)d_in[2];
    if (!v_att)     v_att     = (const float*)d_in[3];
    if (!leaves)    leaves    = d_in[4];
    if (!ancestors) ancestors = d_in[5];

    float* out = (float*)d_out;

    cudaFuncSetAttribute(proj_kernel, cudaFuncAttributeMaxDynamicSharedMemorySize, SM_TOT);
    proj_kernel<<<(VOCAB + 63) / 64, 256, SM_TOT>>>(W_emb, W_att);

    const int total_warps = NCODES / 2;                 // 2 codes per warp
    attn_kernel<<<(total_warps + 3) / 4, 128>>>(b_att, v_att,
                                                leaves, ancestors, out);
}

// round 17
// speedup vs baseline: 1.0594x; 1.0538x over previous
#include <cuda_runtime.h>
#include <cuda_fp16.h>
#include <cstdint>

#define VOCAB   100000
#define NCODES  100000
#define NANC    8
#define EMB     128

// fp16 projected embeddings + fp16 W_emb copy. 78MB -> L2-resident.
__device__ __align__(16) __half g_P1[(size_t)VOCAB * EMB];
__device__ __align__(16) __half g_P2[(size_t)VOCAB * EMB];
__device__ __align__(16) __half g_E [(size_t)VOCAB * EMB];

__device__ __forceinline__ __half2 h2tanh_fast(__half2 x) {
    unsigned r;
    asm("tanh.approx.f16x2 %0, %1;" : "=r"(r) : "r"(*(unsigned*)&x));
    return *(__half2*)&r;
}

// ---------------------------------------------------------------------------
// Fused projection (mma.sync HMMA; tcgen05 unavailable under .target sm_103):
//   P1 = W_emb @ W1, P2 = W_emb @ W2, g_E = fp16(W_emb)   [frozen since R14]
// One block per 64 rows; warps 0-3 half 0, warps 4-7 half 1.
// ---------------------------------------------------------------------------
#define AS_STRIDE 132
#define BP_STRIDE 132
#define SM_AS_BYTES (64 * AS_STRIDE * 2)
#define SM_TOT      (SM_AS_BYTES + 2 * 32 * BP_STRIDE * 8)

__global__ __launch_bounds__(256) void proj_kernel(const float* __restrict__ A,
                                                   const float* __restrict__ Watt) {
    extern __shared__ char smraw[];
    __half* As = (__half*)smraw;
    uint2*  Bp = (uint2*)(smraw + SM_AS_BYTES);

    const int m0 = blockIdx.x * 64;
    const int tid = threadIdx.x;
    const int wid = tid >> 5;
    const int lane = tid & 31;

    // ---- stage A (64 rows) as fp16 + emit g_E (free) ----
#pragma unroll
    for (int i = 0; i < 8; i++) {
        int e = tid + i * 256;
        int m = e >> 5;
        int kc = (e & 31) * 4;
        int gm = m0 + m; if (gm >= VOCAB) gm = VOCAB - 1;
        float4 v = __ldg((const float4*)(A + (size_t)gm * EMB + kc));
        __half2 h0 = __floats2half2_rn(v.x, v.y);
        __half2 h1 = __floats2half2_rn(v.z, v.w);
        uint2 pk; pk.x = *(unsigned*)&h0; pk.y = *(unsigned*)&h1;
        *(uint2*)&As[m * AS_STRIDE + kc] = pk;
        if (m0 + m < VOCAB)
            *(uint2*)&g_E[(size_t)(m0 + m) * EMB + kc] = pk;
    }

    // ---- stage B fragment pairs for both halves ----
#pragma unroll
    for (int i = 0; i < 32; i++) {
        int e = tid + i * 256;
        int h   = e >> 12;
        int rem = e & 4095;
        int j   = rem >> 7;
        int n   = rem & 127;
        int kpa = (j >> 2) * 8 + (j & 3);
        const float* Wh = Watt + (size_t)h * 128 * 128;
        float w0 = __ldg(Wh + (size_t)(2 * kpa)     * 128 + n);
        float w1 = __ldg(Wh + (size_t)(2 * kpa + 1) * 128 + n);
        float w2 = __ldg(Wh + (size_t)(2 * kpa + 8) * 128 + n);
        float w3 = __ldg(Wh + (size_t)(2 * kpa + 9) * 128 + n);
        __half2 ha = __floats2half2_rn(w0, w1);
        __half2 hb = __floats2half2_rn(w2, w3);
        uint2 pr; pr.x = *(unsigned*)&ha; pr.y = *(unsigned*)&hb;
        Bp[(h * 32 + j) * BP_STRIDE + n] = pr;
    }
    __syncthreads();

    // ---- mma mainloop ----
    const int g = lane >> 2;
    const int q = lane & 3;
    const int t2 = q * 2;
    const int half = wid >> 2;
    const int w16 = (wid & 3) * 16;
    const uint2* BpH = Bp + half * 32 * BP_STRIDE;

    float c[16][4];
#pragma unroll
    for (int nt = 0; nt < 16; nt++)
#pragma unroll
        for (int j = 0; j < 4; j++) c[nt][j] = 0.0f;

#pragma unroll
    for (int ks = 0; ks < 8; ks++) {
        const int k0 = ks * 16;
        const unsigned a0 = *(const unsigned*)&As[(w16 + g)     * AS_STRIDE + k0 + t2];
        const unsigned a1 = *(const unsigned*)&As[(w16 + g + 8) * AS_STRIDE + k0 + t2];
        const unsigned a2 = *(const unsigned*)&As[(w16 + g)     * AS_STRIDE + k0 + t2 + 8];
        const unsigned a3 = *(const unsigned*)&As[(w16 + g + 8) * AS_STRIDE + k0 + t2 + 8];
        const uint2* brow = BpH + (ks * 4 + q) * BP_STRIDE;
#pragma unroll
        for (int nt = 0; nt < 16; nt++) {
            const uint2 b = brow[nt * 8 + g];
            asm volatile(
                "mma.sync.aligned.m16n8k16.row.col.f32.f16.f16.f32 "
                "{%0,%1,%2,%3}, {%4,%5,%6,%7}, {%8,%9}, {%0,%1,%2,%3};"
                : "+f"(c[nt][0]), "+f"(c[nt][1]), "+f"(c[nt][2]), "+f"(c[nt][3])
                : "r"(a0), "r"(a1), "r"(a2), "r"(a3), "r"(b.x), "r"(b.y));
        }
    }

    // ---- epilogue: f32 accum -> fp16 pairs ----
    __half* P = half ? g_P2 : g_P1;
    const int row0 = m0 + w16 + g;
    const int row1 = row0 + 8;
#pragma unroll
    for (int nt = 0; nt < 16; nt++) {
        const int col = nt * 8 + t2;
        if (row0 < VOCAB) {
            __half2 h = __floats2half2_rn(c[nt][0], c[nt][1]);
            *(unsigned*)&P[(size_t)row0 * EMB + col] = *(unsigned*)&h;
        }
        if (row1 < VOCAB) {
            __half2 h = __floats2half2_rn(c[nt][2], c[nt][3]);
            *(unsigned*)&P[(size_t)row1 * EMB + col] = *(unsigned*)&h;
        }
    }
}

// ---------------------------------------------------------------------------
// Attention pass: one warp per code (R14 layout: best measured operating
// point, issue-bound at ~80%). Lane l owns columns [4l, 4l+4).
// Issue-slot cuts vs R14:
//   * fp16 MLP (HADD2 / tanh.approx.f16x2 / HFMA2) on the same uint2 regs
//   * distributed tree reduction: lanes progressively specialize to scores
//     (16 shfl instead of 40), softmax on distributed scores (1 exp/lane
//     instead of 8), then 8 shuffle-broadcasts recover the weights.
// All reduction/softmax math stays f32.
// ---------------------------------------------------------------------------
__global__ __launch_bounds__(128, 5) void attn_kernel(const float* __restrict__ b_att,
                                                      const float* __restrict__ v_att,
                                                      const void* __restrict__ leaves,
                                                      const void* __restrict__ ancestors,
                                                      float* __restrict__ out) {
    const int warp = (blockIdx.x * blockDim.x + threadIdx.x) >> 5;
    const int lane = threadIdx.x & 31;
    if (warp >= NCODES) return;
    const int c = lane * 4;

    const float4 bv = __ldg((const float4*)(b_att + c));
    const float4 vv = __ldg((const float4*)(v_att + c));
    const __half2 bh0 = __floats2half2_rn(bv.x, bv.y);
    const __half2 bh1 = __floats2half2_rn(bv.z, bv.w);
    const __half2 vh0 = __floats2half2_rn(vv.x, vv.y);
    const __half2 vh1 = __floats2half2_rn(vv.z, vv.w);

    // ---- dtype probe + ballot (bounded under both interpretations) ----
    int pl = 0, pa = 0;
    if (lane < 8) {
        const size_t dw = (size_t)warp * 8 + lane;
        pl = __ldg((const int*)leaves + dw);
        pa = __ldg((const int*)ancestors + dw);
    }
    const unsigned nzb = __ballot_sync(0xffffffffu, (pl | pa) != 0);
    const bool is64 = ((nzb & 0xAAu) == 0u);

    int wl, wa, mul;
    if (is64) {
        wl = 0; wa = 0;
        if (lane < 16) {
            const size_t dw = (size_t)warp * 16 + lane;
            wl = __ldg((const int*)leaves + dw);
            wa = __ldg((const int*)ancestors + dw);
        }
        mul = 2;
    } else {
        wl = pl; wa = pa; mul = 1;
    }
    int li[NANC], ai[NANC];
#pragma unroll
    for (int a = 0; a < NANC; a++) {
        li[a] = __shfl_sync(0xffffffffu, wl, a * mul);
        ai[a] = __shfl_sync(0xffffffffu, wa, a * mul);
        li[a] = min(max(li[a], 0), VOCAB - 1);
        ai[a] = min(max(ai[a], 0), VOCAB - 1);
    }

    // ---- batch P1/P2 gathers (uint2 = 4 fp16 / lane) ----
    uint2 p1v[NANC], p2v[NANC];
#pragma unroll
    for (int a = 0; a < NANC; a++)
        p1v[a] = __ldg((const uint2*)(g_P1 + (size_t)li[a] * EMB + c));
#pragma unroll
    for (int a = 0; a < NANC; a++)
        p2v[a] = __ldg((const uint2*)(g_P2 + (size_t)ai[a] * EMB + c));

    // ---- fp16 MLP + per-lane partial dots (p1v/p2v die here) ----
    float d[NANC];
#pragma unroll
    for (int a = 0; a < NANC; a++) {
        const __half2 t0 = h2tanh_fast(__hadd2(__hadd2(*(const __half2*)&p1v[a].x,
                                                       *(const __half2*)&p2v[a].x), bh0));
        const __half2 t1 = h2tanh_fast(__hadd2(__hadd2(*(const __half2*)&p1v[a].y,
                                                       *(const __half2*)&p2v[a].y), bh1));
        const __half2 dh = __hfma2(t1, vh1, __hmul2(t0, vh0));
        const float2 df = __half22float2(dh);
        d[a] = df.x + df.y;
    }

    // ---- batch E gathers (overlap reduction latency) ----
    uint2 ev[NANC];
#pragma unroll
    for (int a = 0; a < NANC; a++)
        ev[a] = __ldg((const uint2*)(g_E + (size_t)ai[a] * EMB + c));

    // ---- distributed tree reduction: lanes specialize to scores ----
    // After each butterfly stage, halve the carried score set by lane-group
    // selection. Final: lane group [4a, 4a+4) holds the full sum of score a.
#pragma unroll
    for (int a = 0; a < NANC; a++) d[a] += __shfl_xor_sync(0xffffffffu, d[a], 16);
    float e0 = (lane & 16) ? d[4] : d[0];
    float e1 = (lane & 16) ? d[5] : d[1];
    float e2 = (lane & 16) ? d[6] : d[2];
    float e3 = (lane & 16) ? d[7] : d[3];
    e0 += __shfl_xor_sync(0xffffffffu, e0, 8);
    e1 += __shfl_xor_sync(0xffffffffu, e1, 8);
    e2 += __shfl_xor_sync(0xffffffffu, e2, 8);
    e3 += __shfl_xor_sync(0xffffffffu, e3, 8);
    float f0 = (lane & 8) ? e2 : e0;
    float f1 = (lane & 8) ? e3 : e1;
    f0 += __shfl_xor_sync(0xffffffffu, f0, 4);
    f1 += __shfl_xor_sync(0xffffffffu, f1, 4);
    float s = (lane & 4) ? f1 : f0;
    s += __shfl_xor_sync(0xffffffffu, s, 2);
    s += __shfl_xor_sync(0xffffffffu, s, 1);
    // lane holds score index a = 4*b4 + 2*b3 + b2 of its (b4,b3,b2) group.

    // ---- softmax on distributed scores (1 exp per lane) ----
    float mx = s;
    mx = fmaxf(mx, __shfl_xor_sync(0xffffffffu, mx, 4));
    mx = fmaxf(mx, __shfl_xor_sync(0xffffffffu, mx, 8));
    mx = fmaxf(mx, __shfl_xor_sync(0xffffffffu, mx, 16));
    const float ex = __expf(s - mx);
    float sum = ex;
    sum += __shfl_xor_sync(0xffffffffu, sum, 4);
    sum += __shfl_xor_sync(0xffffffffu, sum, 8);
    sum += __shfl_xor_sync(0xffffffffu, sum, 16);
    const float w = ex / sum;

    // ---- recover w[a] via broadcast (score a lives in lanes 4a..4a+3) ----
    float accx = 0.f, accy = 0.f, accz = 0.f, accw = 0.f;
#pragma unroll
    for (int a = 0; a < NANC; a++) {
        const float wa_ = __shfl_sync(0xffffffffu, w, a * 4);
        const float2 ea = __half22float2(*(const __half2*)&ev[a].x);
        const float2 eb = __half22float2(*(const __half2*)&ev[a].y);
        accx += wa_ * ea.x;
        accy += wa_ * ea.y;
        accz += wa_ * eb.x;
        accw += wa_ * eb.y;
    }
    *(float4*)(out + (size_t)warp * EMB + c) = make_float4(accx, accy, accz, accw);
}

extern "C" void kernel_launch(void* const* d_in, const int* in_sizes, int n_in,
                              void* d_out, int out_size) {
    const float* W_emb = nullptr;
    const float* W_att = nullptr;
    const float* b_att = nullptr;
    const float* v_att = nullptr;
    const void*  leaves = nullptr;
    const void*  ancestors = nullptr;

    for (int i = 0; i < n_in; i++) {
        const int s = in_sizes[i];
        if (s == VOCAB * EMB)            { W_emb = (const float*)d_in[i]; }
        else if (s == 2 * EMB * EMB)     { W_att = (const float*)d_in[i]; }
        else if (s == EMB)               { if (!b_att) b_att = (const float*)d_in[i];
                                           else        v_att = (const float*)d_in[i]; }
        else if (s == NCODES * NANC)     { if (!leaves) leaves = d_in[i];
                                           else         ancestors = d_in[i]; }
    }
    if (!W_emb)     W_emb     = (const float*)d_in[0];
    if (!W_att)     W_att     = (const float*)d_in[1];
    if (!b_att)     b_att     = (const float*)d_in[2];
    if (!v_att)     v_att     = (const float*)d_in[3];
    if (!leaves)    leaves    = d_in[4];
    if (!ancestors) ancestors = d_in[5];

    float* out = (float*)d_out;

    cudaFuncSetAttribute(proj_kernel, cudaFuncAttributeMaxDynamicSharedMemorySize, SM_TOT);
    proj_kernel<<<(VOCAB + 63) / 64, 256, SM_TOT>>>(W_emb, W_att);

    const int total_threads = NCODES * 32;
    attn_kernel<<<(total_threads + 127) / 128, 128>>>(b_att, v_att,
                                                      leaves, ancestors, out);
}